// round 5
// baseline (speedup 1.0000x reference)
#include <cuda_runtime.h>
#include <cstdint>

// out[b,t] = cumsum_t( relu(x @ Wh^T + bh) ) + (x @ Wb^T + bb)
//   x [16384,1024] f32, Wh [512,1024] f32, bh[512], Wb[1,1024], bb[1]
//
// mma.sync tf32. 16 warps, CTA 64x512, warp tile 32x64 (mw = wid&1,
// nw = wid>>1). Wh pre-rounded to tf32 + k-permuted in __device__ scratch.
// x rounded+permuted per chunk (4 elems/thread). k-permute makes all
// fragment loads LDS.128 (pitch 36 => conflict-free). In-register epilogue.

#define DDIM   1024
#define TDIM   512
#define BROWS  16384
#define MTILE  64
#define KCHUNK 32
#define NCHUNKS 32
#define NTHREADS 512
#define P      36

// smem offsets (floats)
#define WS0    0
#define WS1    18432
#define XR0    36864
#define XR1    38912
#define XT0    40960
#define XT1    43264
#define WB_O   45568
#define BH_O   46592
#define BASE_O 47104
#define SEG_O  47168
#define SMEM_F 47680
#define SMEM_BYTES (SMEM_F * 4)   // 190720

__device__ float g_whs[TDIM * DDIM];   // pre-rounded, k-permuted Wh

__device__ __forceinline__ uint32_t f2tf(float f) {
    uint32_t r;
    asm("cvt.rna.tf32.f32 %0, %1;" : "=r"(r) : "f"(f));
    return r;
}
__device__ __forceinline__ void mma_tf32(float* c, uint32_t a0, uint32_t a1,
                                         uint32_t a2, uint32_t a3,
                                         uint32_t b0, uint32_t b1) {
    asm volatile(
        "mma.sync.aligned.m16n8k8.row.col.f32.tf32.tf32.f32 "
        "{%0,%1,%2,%3}, {%4,%5,%6,%7}, {%8,%9}, {%0,%1,%2,%3};"
        : "+f"(c[0]), "+f"(c[1]), "+f"(c[2]), "+f"(c[3])
        : "r"(a0), "r"(a1), "r"(a2), "r"(a3), "r"(b0), "r"(b1));
}
__device__ __forceinline__ void cp16(float* dst_s, const float* src_g) {
    uint32_t d = (uint32_t)__cvta_generic_to_shared(dst_s);
    asm volatile("cp.async.cg.shared.global [%0], [%1], 16;" :: "r"(d), "l"(src_g));
}

// prepass: round Wh to tf32 (RN), store k-permuted:
//   k = 32*c + 8*s + j  ->  phys = 32*c + 8*(j&3) + 2*s + (j>>2)
__global__ void __launch_bounds__(256) prep_wh_kernel(const float* __restrict__ Wh) {
    const int row = blockIdx.x;
    const int k4  = threadIdx.x * 4;
    float4 v = *(const float4*)(Wh + (size_t)row * DDIM + k4);
    #pragma unroll
    for (int e = 0; e < 4; e++) {
        int k = k4 + e;
        int c = k >> 5, k5 = k & 31, s = k5 >> 3, j = k5 & 7;
        int phys = c * 32 + 8 * (j & 3) + 2 * s + (j >> 2);
        g_whs[(size_t)row * DDIM + phys] = __uint_as_float(f2tf(((const float*)&v)[e]));
    }
}

__global__ void __launch_bounds__(NTHREADS, 1)
surv_mma16_kernel(const float* __restrict__ x,
                  const float* __restrict__ bh,
                  const float* __restrict__ Wb,
                  const float* __restrict__ bb,
                  float* __restrict__ out)
{
    extern __shared__ float sm[];
    float* wb_s   = sm + WB_O;
    float* bh_s   = sm + BH_O;
    float* base_s = sm + BASE_O;
    float* seg_s  = sm + SEG_O;

    const int tid  = threadIdx.x;
    const int wid  = tid >> 5;
    const int lane = tid & 31;
    const int mw   = wid & 1;       // 32-row group
    const int nw   = wid >> 1;      // 64-col group
    const int l4   = lane >> 2;
    const int lk   = lane & 3;
    const int row0 = blockIdx.x * MTILE;

    // hoisted per-thread load addressing
    const int rb  = tid >> 3;       // 0..63
    const int seg = tid & 7;        // 16B segment
    const float* wsrc = g_whs + (size_t)rb * DDIM + seg * 4;
    const float* xsrc = x + (size_t)(row0 + rb) * DDIM + seg * 4;
    float* wdst0 = sm + WS0 + rb * P + seg * 4;
    float* xdst0 = sm + XR0 + rb * 32 + seg * 4;

    auto issue = [&](int c, int buf) {
        float* wd = wdst0 + (buf ? (WS1 - WS0) : 0);
        float* xd = xdst0 + (buf ? (XR1 - XR0) : 0);
        const float* ws = wsrc + c * KCHUNK;
        #pragma unroll
        for (int i = 0; i < 8; i++)
            cp16(wd + i * 64 * P, ws + (size_t)i * 64 * DDIM);
        cp16(xd, xsrc + c * KCHUNK);
    };

    float acc[2][8][4];
    #pragma unroll
    for (int i = 0; i < 2; i++)
        #pragma unroll
        for (int j = 0; j < 8; j++)
            #pragma unroll
            for (int q = 0; q < 4; q++) acc[i][j][q] = 0.f;
    float bacc = 0.f;

    issue(0, 0); asm volatile("cp.async.commit_group;" ::: "memory");
    issue(1, 1); asm volatile("cp.async.commit_group;" ::: "memory");

    // preload Wb (1024) + bh (512)
    wb_s[tid]       = Wb[tid];
    wb_s[tid + 512] = Wb[tid + 512];
    bh_s[tid & 511] = bh[tid & 511];

    // convert-phase addressing: phys = 8*e + pb, pb = 2*(seg>>1) + (seg&1)
    const int pb = 2 * (seg >> 1) + (seg & 1);

    for (int c = 0; c < NCHUNKS; c++) {
        if (c < NCHUNKS - 1) asm volatile("cp.async.wait_group 1;" ::: "memory");
        else                 asm volatile("cp.async.wait_group 0;" ::: "memory");
        __syncthreads();

        const int buf = c & 1;
        const float* wsb = sm + (buf ? WS1 : WS0);
        const float* xrb = sm + (buf ? XR1 : XR0);
        float*       xtb = sm + (buf ? XT1 : XT0);

        // ---- convert x tile (4 elems/thread) + base GEMV partial ----
        {
            float4 v = *(const float4*)(xrb + rb * 32 + seg * 4);
            float* xo = xtb + rb * P + pb;
            xo[0]  = __uint_as_float(f2tf(v.x));
            xo[8]  = __uint_as_float(f2tf(v.y));
            xo[16] = __uint_as_float(f2tf(v.z));
            xo[24] = __uint_as_float(f2tf(v.w));
            float4 wv = *(const float4*)(wb_s + c * KCHUNK + seg * 4);
            bacc = fmaf(v.x, wv.x, bacc);
            bacc = fmaf(v.y, wv.y, bacc);
            bacc = fmaf(v.z, wv.z, bacc);
            bacc = fmaf(v.w, wv.w, bacc);
        }
        __syncthreads();

        // ---- MMA: warp tile 32x64 ----
        const float* xa = xtb + (mw * 32 + l4) * P + 8 * lk;
        const float* wp = wsb + (nw * 64 + l4) * P + 8 * lk;
        #pragma unroll
        for (int sp = 0; sp < 2; sp++) {
            uint4 af0a = *(const uint4*)(xa + 4 * sp);
            uint4 af0b = *(const uint4*)(xa + 8 * P + 4 * sp);
            uint4 af1a = *(const uint4*)(xa + 16 * P + 4 * sp);
            uint4 af1b = *(const uint4*)(xa + 24 * P + 4 * sp);
            #pragma unroll
            for (int j = 0; j < 8; j++) {
                uint4 bf = *(const uint4*)(wp + j * 8 * P + 4 * sp);
                mma_tf32(acc[0][j], af0a.x, af0b.x, af0a.y, af0b.y, bf.x, bf.y);
                mma_tf32(acc[1][j], af1a.x, af1b.x, af1a.y, af1b.y, bf.x, bf.y);
                mma_tf32(acc[0][j], af0a.z, af0b.z, af0a.w, af0b.w, bf.z, bf.w);
                mma_tf32(acc[1][j], af1a.z, af1b.z, af1a.w, af1b.w, bf.z, bf.w);
            }
        }
        __syncthreads();
        if (c + 2 < NCHUNKS) {
            issue(c + 2, buf);
            asm volatile("cp.async.commit_group;" ::: "memory");
        }
    }

    // ---- base reduce: 8 lanes per row ----
    bacc += __shfl_down_sync(0xffffffffu, bacc, 4, 8);
    bacc += __shfl_down_sync(0xffffffffu, bacc, 2, 8);
    bacc += __shfl_down_sync(0xffffffffu, bacc, 1, 8);
    if (seg == 0) base_s[rb] = bacc;

    // ---- per-row segmented scan over this warp's 64 cols ----
    float2 bhv[8];
    #pragma unroll
    for (int j = 0; j < 8; j++)
        bhv[j] = *(const float2*)(bh_s + nw * 64 + 8 * j + 2 * lk);

    #pragma unroll
    for (int i = 0; i < 2; i++) {
        #pragma unroll
        for (int hh = 0; hh < 2; hh++) {
            const int row = mw * 32 + 16 * i + 8 * hh + l4;
            float carry = 0.f;
            #pragma unroll
            for (int j = 0; j < 8; j++) {
                float v0 = fmaxf(acc[i][j][2 * hh]     + bhv[j].x, 0.f);
                float v1 = fmaxf(acc[i][j][2 * hh + 1] + bhv[j].y, 0.f);
                float p = v0 + v1;
                float incl = p, t;
                t = __shfl_up_sync(0xffffffffu, incl, 1, 4); if (lk >= 1) incl += t;
                t = __shfl_up_sync(0xffffffffu, incl, 2, 4); if (lk >= 2) incl += t;
                float excl = incl - p;
                acc[i][j][2 * hh]     = carry + excl + v0;
                acc[i][j][2 * hh + 1] = carry + incl;
                carry += __shfl_sync(0xffffffffu, incl, 3, 4);
            }
            if (lk == 0) seg_s[row * 8 + nw] = carry;
        }
    }
    __syncthreads();

    // ---- cross-warp segment prefix + base, store ----
    const float bbv = bb[0];
    #pragma unroll
    for (int i = 0; i < 2; i++) {
        #pragma unroll
        for (int hh = 0; hh < 2; hh++) {
            const int row = mw * 32 + 16 * i + 8 * hh + l4;
            float g = base_s[row] + bbv;
            #pragma unroll
            for (int s = 0; s < 8; s++)
                if (s < nw) g += seg_s[row * 8 + s];
            float* orow = out + (size_t)(row0 + row) * TDIM + nw * 64 + 2 * lk;
            #pragma unroll
            for (int j = 0; j < 8; j++) {
                float2 o;
                o.x = acc[i][j][2 * hh]     + g;
                o.y = acc[i][j][2 * hh + 1] + g;
                *(float2*)(orow + 8 * j) = o;
            }
        }
    }
}

extern "C" void kernel_launch(void* const* d_in, const int* in_sizes, int n_in,
                              void* d_out, int out_size)
{
    const float* x  = (const float*)d_in[0];
    const float* Wh = (const float*)d_in[1];
    const float* bh = (const float*)d_in[2];
    const float* Wb = (const float*)d_in[3];
    const float* bb = (const float*)d_in[4];
    float* out = (float*)d_out;
    (void)in_sizes; (void)n_in; (void)out_size;

    static bool attr_set = false;
    if (!attr_set) {
        cudaFuncSetAttribute(surv_mma16_kernel,
                             cudaFuncAttributeMaxDynamicSharedMemorySize,
                             SMEM_BYTES);
        attr_set = true;
    }

    prep_wh_kernel<<<TDIM, 256>>>(Wh);
    surv_mma16_kernel<<<BROWS / MTILE, NTHREADS, SMEM_BYTES>>>(x, bh, Wb, bb, out);
}

// round 6
// speedup vs baseline: 1.9665x; 1.9665x over previous
#include <cuda_runtime.h>
#include <cuda_fp16.h>
#include <cstdint>

// out[b,t] = cumsum_t( relu(x @ Wh^T + bh) ) + (x @ Wb^T + bb)
//   x [16384,1024] f32, Wh [512,1024] f32, bh[512], Wb[1,1024], bb[1]
//
// fp16 mma.sync m16n8k16 (same 10-bit mantissa as tf32; operands are
// range-safe). Wh pre-converted to fp16, pre-k-permuted and pre-XOR-swizzled
// in a prepass so cp.async lands MMA-ready tiles. CTA 64x512, 16 warps,
// warp tile 32x64, KCHUNK=64 (16 iters). 2-stage ws, 3-stage xr, 2-stage xs
// with pipelined in-kernel x->fp16 convert. In-register scan epilogue.

#define DDIM   1024
#define TDIM   512
#define BROWS  16384
#define MTILE  64
#define KCHUNK 64
#define NCH    16
#define NTHREADS 512

// smem byte offsets
#define WS_O   0                      // 2 x 65536
#define XR_O   131072                 // 3 x 16384 (raw fp32 x)
#define XS_O   180224                 // 2 x 8192  (fp16 permuted x)
#define WB_O   196608                 // 1024 f32
#define BH_O   200704                 // 512 f32
#define BASE_O 202752                 // 64 f32
#define SEG_O  203008                 // 512 f32
#define SMEM_BYTES 205056

__device__ __half g_whs[TDIM * DDIM];   // fp16, per-chunk [c][row][64], permuted+swizzled

__device__ __forceinline__ void mma_f16(float* c, uint32_t a0, uint32_t a1,
                                        uint32_t a2, uint32_t a3,
                                        uint32_t b0, uint32_t b1) {
    asm volatile(
        "mma.sync.aligned.m16n8k16.row.col.f32.f16.f16.f32 "
        "{%0,%1,%2,%3}, {%4,%5,%6,%7}, {%8,%9}, {%0,%1,%2,%3};"
        : "+f"(c[0]), "+f"(c[1]), "+f"(c[2]), "+f"(c[3])
        : "r"(a0), "r"(a1), "r"(a2), "r"(a3), "r"(b0), "r"(b1));
}
__device__ __forceinline__ void cp16(void* dst_s, const void* src_g) {
    uint32_t d = (uint32_t)__cvta_generic_to_shared(dst_s);
    asm volatile("cp.async.cg.shared.global [%0], [%1], 16;" :: "r"(d), "l"(src_g));
}
#define CP_COMMIT() asm volatile("cp.async.commit_group;" ::: "memory")

// prepass: Wh fp32 -> fp16, layout g_whs[c][row][64 fp16] with
//   k = 64c + 32G + 16u + 8v + 2l + w  ->  within-row fp16 idx:
//   chunk16 = (4G + l) ^ (4*(row&1)); half = chunk16*8 + 4u + 2v + w
__global__ void __launch_bounds__(256) prep_wh_kernel(const float* __restrict__ Wh) {
    const int r  = blockIdx.x;
    const int k4 = threadIdx.x * 4;
    float4 v = *(const float4*)(Wh + (size_t)r * DDIM + k4);
    #pragma unroll
    for (int e = 0; e < 4; e++) {
        int k  = k4 + e;
        int c  = k >> 6;
        int k6 = k & 63;
        int G  = (k6 >> 5) & 1;
        int k5 = k6 & 31;
        int u  = (k5 >> 4) & 1, vv = (k5 >> 3) & 1, l = (k5 >> 1) & 3, w = k5 & 1;
        int ch = (4 * G + l) ^ ((r & 1) << 2);
        int half_idx = ch * 8 + 4 * u + 2 * vv + w;
        g_whs[((size_t)c * TDIM + r) * 64 + half_idx] =
            __float2half_rn(((const float*)&v)[e]);
    }
}

__global__ void __launch_bounds__(NTHREADS, 1)
surv_f16_kernel(const float* __restrict__ x,
                const float* __restrict__ bh,
                const float* __restrict__ Wb,
                const float* __restrict__ bb,
                float* __restrict__ out)
{
    extern __shared__ char smc[];
    float* wb_s   = (float*)(smc + WB_O);
    float* bh_s   = (float*)(smc + BH_O);
    float* base_s = (float*)(smc + BASE_O);
    float* seg_s  = (float*)(smc + SEG_O);

    const int tid  = threadIdx.x;
    const int wid  = tid >> 5;
    const int lane = tid & 31;
    const int mw   = wid & 1;          // 32-row group
    const int nw   = wid >> 1;         // 64-col group
    const int l4   = lane >> 2;
    const int lk   = lane & 3;
    const int row0 = blockIdx.x * MTILE;

    // ---- async copy issuers ----
    const char* wsrc0 = (const char*)g_whs + (tid >> 3) * 128 + (tid & 7) * 16;
    auto issue_ws = [&](int c) {
        const char* src = wsrc0 + (size_t)c * 65536;
        char* dst = smc + WS_O + (c & 1) * 65536 + (tid >> 3) * 128 + (tid & 7) * 16;
        #pragma unroll
        for (int i = 0; i < 8; i++)
            cp16(dst + i * 8192, src + i * 8192);
        CP_COMMIT();
    };
    const float* xsrc0 = x + (size_t)(row0 + (tid >> 4)) * DDIM + (tid & 15) * 4;
    auto issue_xr = [&](int c) {
        const float* src = xsrc0 + c * KCHUNK;
        float* dst = (float*)(smc + XR_O + (c % 3) * 16384) + (tid >> 4) * 64 + (tid & 15) * 4;
        cp16(dst, src);
        cp16(dst + 32 * 64, src + (size_t)32 * DDIM);
        CP_COMMIT();
    };

    // ---- convert (chunk cc): xr -> xs (fp16 permuted+swizzled) + base GEMV ----
    const int crow = tid >> 3;         // 0..63
    const int cm   = tid & 7;          // 0..7 (8 k-values each)
    const int cG = cm >> 2, cm2 = cm & 3;
    const int wordsel = 2 * (cm2 >> 1) + (cm2 & 1);
    const int rsw = (crow & 1) << 2;
    float bacc = 0.f;
    auto convert = [&](int cc) {
        const float* xrp = (float*)(smc + XR_O + (cc % 3) * 16384) + crow * 64 + cm * 8;
        float4 v0 = *(const float4*)(xrp);
        float4 v1 = *(const float4*)(xrp + 4);
        const float* wbp = wb_s + cc * KCHUNK + cm * 8;
        float4 w0 = *(const float4*)(wbp);
        float4 w1 = *(const float4*)(wbp + 4);
        bacc = fmaf(v0.x, w0.x, bacc); bacc = fmaf(v0.y, w0.y, bacc);
        bacc = fmaf(v0.z, w0.z, bacc); bacc = fmaf(v0.w, w0.w, bacc);
        bacc = fmaf(v1.x, w1.x, bacc); bacc = fmaf(v1.y, w1.y, bacc);
        bacc = fmaf(v1.z, w1.z, bacc); bacc = fmaf(v1.w, w1.w, bacc);
        __half2* xsp = (__half2*)(smc + XS_O + (cc & 1) * 8192 + crow * 128);
        xsp[(((4 * cG + 0) ^ rsw) << 2) + wordsel] = __floats2half2_rn(v0.x, v0.y);
        xsp[(((4 * cG + 1) ^ rsw) << 2) + wordsel] = __floats2half2_rn(v0.z, v0.w);
        xsp[(((4 * cG + 2) ^ rsw) << 2) + wordsel] = __floats2half2_rn(v1.x, v1.y);
        xsp[(((4 * cG + 3) ^ rsw) << 2) + wordsel] = __floats2half2_rn(v1.z, v1.w);
    };

    float acc[2][8][4];
    #pragma unroll
    for (int i = 0; i < 2; i++)
        #pragma unroll
        for (int j = 0; j < 8; j++)
            #pragma unroll
            for (int q = 0; q < 4; q++) acc[i][j][q] = 0.f;

    // ---- prologue: groups in order xr0, ws0, xr1, ws1, xr2 ----
    issue_xr(0); issue_ws(0); issue_xr(1); issue_ws(1); issue_xr(2);

    wb_s[tid]       = Wb[tid];
    wb_s[tid + 512] = Wb[tid + 512];
    bh_s[tid & 511] = bh[tid & 511];

    asm volatile("cp.async.wait_group 4;" ::: "memory");   // xr0 done
    __syncthreads();
    convert(0);

    // fragment base addresses
    const int arow_base = mw * 32 + l4;

    for (int c = 0; c < NCH; c++) {
        if (c <= 13)      asm volatile("cp.async.wait_group 2;" ::: "memory");
        else if (c == 14) asm volatile("cp.async.wait_group 1;" ::: "memory");
        else              asm volatile("cp.async.wait_group 0;" ::: "memory");
        __syncthreads();   // data + converts visible

        if (c + 1 < NCH) convert(c + 1);

        const char* xsb = smc + XS_O + (c & 1) * 8192;
        const char* wsb = smc + WS_O + (c & 1) * 65536;
        #pragma unroll
        for (int G = 0; G < 2; G++) {
            uint4 LA[4];
            #pragma unroll
            for (int r4 = 0; r4 < 4; r4++) {
                int row = arow_base + 8 * r4;
                LA[r4] = *(const uint4*)(xsb + row * 128 +
                                         ((G ^ (row & 1)) << 6) + (lk << 4));
            }
            #pragma unroll
            for (int j = 0; j < 8; j++) {
                int t = nw * 64 + 8 * j + l4;
                uint4 LB = *(const uint4*)(wsb + t * 128 +
                                           ((G ^ (t & 1)) << 6) + (lk << 4));
                mma_f16(acc[0][j], LA[0].x, LA[1].x, LA[0].y, LA[1].y, LB.x, LB.y);
                mma_f16(acc[1][j], LA[2].x, LA[3].x, LA[2].y, LA[3].y, LB.x, LB.y);
                mma_f16(acc[0][j], LA[0].z, LA[1].z, LA[0].w, LA[1].w, LB.z, LB.w);
                mma_f16(acc[1][j], LA[2].z, LA[3].z, LA[2].w, LA[3].w, LB.z, LB.w);
            }
        }
        __syncthreads();   // all MMA reads of ws[c&1] done before overwrite
        if (c + 2 < NCH) issue_ws(c + 2);
        if (c + 3 < NCH) issue_xr(c + 3);
    }

    // ---- base reduce: 8 lanes (cm) per row ----
    bacc += __shfl_down_sync(0xffffffffu, bacc, 4, 8);
    bacc += __shfl_down_sync(0xffffffffu, bacc, 2, 8);
    bacc += __shfl_down_sync(0xffffffffu, bacc, 1, 8);
    if (cm == 0) base_s[crow] = bacc;

    // ---- per-row segmented scan over this warp's 64 cols ----
    float2 bhv[8];
    #pragma unroll
    for (int j = 0; j < 8; j++)
        bhv[j] = *(const float2*)(bh_s + nw * 64 + 8 * j + 2 * lk);

    #pragma unroll
    for (int i = 0; i < 2; i++) {
        #pragma unroll
        for (int hh = 0; hh < 2; hh++) {
            const int row = mw * 32 + 16 * i + 8 * hh + l4;
            float carry = 0.f;
            #pragma unroll
            for (int j = 0; j < 8; j++) {
                float v0 = fmaxf(acc[i][j][2 * hh]     + bhv[j].x, 0.f);
                float v1 = fmaxf(acc[i][j][2 * hh + 1] + bhv[j].y, 0.f);
                float p = v0 + v1;
                float incl = p, t;
                t = __shfl_up_sync(0xffffffffu, incl, 1, 4); if (lk >= 1) incl += t;
                t = __shfl_up_sync(0xffffffffu, incl, 2, 4); if (lk >= 2) incl += t;
                float excl = incl - p;
                acc[i][j][2 * hh]     = carry + excl + v0;
                acc[i][j][2 * hh + 1] = carry + incl;
                carry += __shfl_sync(0xffffffffu, incl, 3, 4);
            }
            if (lk == 0) seg_s[row * 8 + nw] = carry;
        }
    }
    __syncthreads();

    // ---- cross-warp segment prefix + base, store ----
    const float bbv = bb[0];
    #pragma unroll
    for (int i = 0; i < 2; i++) {
        #pragma unroll
        for (int hh = 0; hh < 2; hh++) {
            const int row = mw * 32 + 16 * i + 8 * hh + l4;
            float g = base_s[row] + bbv;
            #pragma unroll
            for (int s = 0; s < 8; s++)
                if (s < nw) g += seg_s[row * 8 + s];
            float* orow = out + (size_t)(row0 + row) * TDIM + nw * 64 + 2 * lk;
            #pragma unroll
            for (int j = 0; j < 8; j++) {
                float2 o;
                o.x = acc[i][j][2 * hh]     + g;
                o.y = acc[i][j][2 * hh + 1] + g;
                *(float2*)(orow + 8 * j) = o;
            }
        }
    }
}

extern "C" void kernel_launch(void* const* d_in, const int* in_sizes, int n_in,
                              void* d_out, int out_size)
{
    const float* x  = (const float*)d_in[0];
    const float* Wh = (const float*)d_in[1];
    const float* bh = (const float*)d_in[2];
    const float* Wb = (const float*)d_in[3];
    const float* bb = (const float*)d_in[4];
    float* out = (float*)d_out;
    (void)in_sizes; (void)n_in; (void)out_size;

    static bool attr_set = false;
    if (!attr_set) {
        cudaFuncSetAttribute(surv_f16_kernel,
                             cudaFuncAttributeMaxDynamicSharedMemorySize,
                             SMEM_BYTES);
        attr_set = true;
    }

    prep_wh_kernel<<<TDIM, 256>>>(Wh);
    surv_f16_kernel<<<BROWS / MTILE, NTHREADS, SMEM_BYTES>>>(x, bh, Wb, bb, out);
}

// round 7
// speedup vs baseline: 2.0985x; 1.0671x over previous
#include <cuda_runtime.h>
#include <cuda_fp16.h>
#include <cstdint>

// out[b,t] = cumsum_t( relu(x @ Wh^T + bh) ) + (x @ Wb^T + bb)
//   x [16384,1024] f32, Wh [512,1024] f32, bh[512], Wb[1,1024], bb[1]
//
// fp16 mma.sync m16n8k16. CTA 64x512, 16 warps, warp tile 32x64, KCHUNK=64.
// Wh pre-converted/permuted/swizzled to g_whs (prepass); 3-stage cp.async ws
// ring with ONE barrier per chunk. x: gmem->regs (prefetch 1 chunk) -> fp16
// convert -> STS to 2-stage xs. Induction-free smem addressing.
// In-register scan epilogue + fused fp32 base GEMV.

#define DDIM   1024
#define TDIM   512
#define BROWS  16384
#define MTILE  64
#define KCHUNK 64
#define NCH    16
#define NTHREADS 512

// smem byte offsets
#define WS_O   0                      // 3 x 65536 ws ring
#define XS_O   196608                 // 2 x 8192 fp16 x
#define WB_O   212992                 // 1024 f32
#define BH_O   217088                 // 512 f32
#define BASE_O 219136                 // 64 f32
#define SEG_O  219392                 // 512 f32
#define SMEM_BYTES 221440

__device__ __half g_whs[TDIM * DDIM];   // [chunk][row][64], permuted+swizzled

__device__ __forceinline__ void mma_f16(float* c, uint32_t a0, uint32_t a1,
                                        uint32_t a2, uint32_t a3,
                                        uint32_t b0, uint32_t b1) {
    asm volatile(
        "mma.sync.aligned.m16n8k16.row.col.f32.f16.f16.f32 "
        "{%0,%1,%2,%3}, {%4,%5,%6,%7}, {%8,%9}, {%0,%1,%2,%3};"
        : "+f"(c[0]), "+f"(c[1]), "+f"(c[2]), "+f"(c[3])
        : "r"(a0), "r"(a1), "r"(a2), "r"(a3), "r"(b0), "r"(b1));
}
__device__ __forceinline__ void cp16(void* dst_s, const void* src_g) {
    uint32_t d = (uint32_t)__cvta_generic_to_shared(dst_s);
    asm volatile("cp.async.cg.shared.global [%0], [%1], 16;" :: "r"(d), "l"(src_g));
}
#define CP_COMMIT() asm volatile("cp.async.commit_group;" ::: "memory")

// prepass: Wh fp32 -> fp16, layout g_whs[c][row][64] with
//   k = 64c + 32G + 16u + 8v + 2l + w ->
//   chunk16 = (4G + l) ^ (4*(row&1)); half_idx = chunk16*8 + 4u + 2v + w
__global__ void __launch_bounds__(256) prep_wh_kernel(const float* __restrict__ Wh) {
    const int r  = blockIdx.x;
    const int k4 = threadIdx.x * 4;
    float4 v = *(const float4*)(Wh + (size_t)r * DDIM + k4);
    #pragma unroll
    for (int e = 0; e < 4; e++) {
        int k  = k4 + e;
        int c  = k >> 6;
        int k6 = k & 63;
        int G  = (k6 >> 5) & 1;
        int k5 = k6 & 31;
        int u  = (k5 >> 4) & 1, vv = (k5 >> 3) & 1, l = (k5 >> 1) & 3, w = k5 & 1;
        int ch = (4 * G + l) ^ ((r & 1) << 2);
        int half_idx = ch * 8 + 4 * u + 2 * vv + w;
        g_whs[((size_t)c * TDIM + r) * 64 + half_idx] =
            __float2half_rn(((const float*)&v)[e]);
    }
}

__global__ void __launch_bounds__(NTHREADS, 1)
surv_f16b_kernel(const float* __restrict__ x,
                 const float* __restrict__ bh,
                 const float* __restrict__ Wb,
                 const float* __restrict__ bb,
                 float* __restrict__ out)
{
    extern __shared__ char smc[];
    float* wb_s   = (float*)(smc + WB_O);
    float* bh_s   = (float*)(smc + BH_O);
    float* base_s = (float*)(smc + BASE_O);
    float* seg_s  = (float*)(smc + SEG_O);

    const int tid  = threadIdx.x;
    const int wid  = tid >> 5;
    const int lane = tid & 31;
    const int mw   = wid & 1;          // 32-row group
    const int nw   = wid >> 1;         // 64-col group
    const int l4   = lane >> 2;
    const int lk   = lane & 3;
    const int row0 = blockIdx.x * MTILE;
    const int sw6  = (l4 & 1) << 6;    // swizzle selector (per-thread const)

    // ws copy addressing (thread covers rows (tid>>3)+64i, 16B seg (tid&7))
    const char* wsrc0 = (const char*)g_whs + (tid >> 3) * 128 + (tid & 7) * 16;
    char*       wdst0 = smc + WS_O + (tid >> 3) * 128 + (tid & 7) * 16;

    // convert addressing: crow = row (0..63), cm = 8-float segment (0..7)
    const int crow = tid >> 3;
    const int cm   = tid & 7;
    const int cG   = cm >> 2, cm2 = cm & 3;
    const int wordsel = 2 * (cm2 >> 1) + (cm2 & 1);
    const int rsw  = (crow & 1) << 2;
    const float* xsrc = x + (size_t)(row0 + crow) * DDIM + cm * 8;

    float acc[2][8][4];
    #pragma unroll
    for (int i = 0; i < 2; i++)
        #pragma unroll
        for (int j = 0; j < 8; j++)
            #pragma unroll
            for (int q = 0; q < 4; q++) acc[i][j][q] = 0.f;
    float bacc = 0.f;

    // preload Wb + bh
    wb_s[tid]       = Wb[tid];
    wb_s[tid + 512] = Wb[tid + 512];
    bh_s[tid & 511] = bh[tid & 511];

    // ws prologue: stages 0 and 1 (2 commit groups)
    #pragma unroll
    for (int i = 0; i < 8; i++) cp16(wdst0 + i * 8192, wsrc0 + i * 8192);
    CP_COMMIT();
    #pragma unroll
    for (int i = 0; i < 8; i++) cp16(wdst0 + 65536 + i * 8192, wsrc0 + 65536 + i * 8192);
    CP_COMMIT();

    __syncthreads();   // wb_s visible for convert(0)

    // x chunk0 -> convert into xs stage 0 ; prefetch chunk1
    float4 px0 = *(const float4*)(xsrc);
    float4 px1 = *(const float4*)(xsrc + 4);
    {
        const float* wbp = wb_s + cm * 8;
        float4 w0 = *(const float4*)(wbp);
        float4 w1 = *(const float4*)(wbp + 4);
        bacc = fmaf(px0.x, w0.x, bacc); bacc = fmaf(px0.y, w0.y, bacc);
        bacc = fmaf(px0.z, w0.z, bacc); bacc = fmaf(px0.w, w0.w, bacc);
        bacc = fmaf(px1.x, w1.x, bacc); bacc = fmaf(px1.y, w1.y, bacc);
        bacc = fmaf(px1.z, w1.z, bacc); bacc = fmaf(px1.w, w1.w, bacc);
        __half2* xsp = (__half2*)(smc + XS_O + crow * 128);
        xsp[(((4 * cG + 0) ^ rsw) << 2) + wordsel] = __floats2half2_rn(px0.x, px0.y);
        xsp[(((4 * cG + 1) ^ rsw) << 2) + wordsel] = __floats2half2_rn(px0.z, px0.w);
        xsp[(((4 * cG + 2) ^ rsw) << 2) + wordsel] = __floats2half2_rn(px1.x, px1.y);
        xsp[(((4 * cG + 3) ^ rsw) << 2) + wordsel] = __floats2half2_rn(px1.z, px1.w);
    }
    px0 = *(const float4*)(xsrc + 64);
    px1 = *(const float4*)(xsrc + 68);

    int ws_rd = 0;          // ring offset of stage for chunk c
    int ws_wr = 131072;     // ring offset for issuing chunk c+2
    int xs_rd = 0;

    #pragma unroll 1
    for (int c = 0; c < NCH; c++) {
        if (c == NCH - 1) asm volatile("cp.async.wait_group 0;" ::: "memory");
        else              asm volatile("cp.async.wait_group 1;" ::: "memory");
        __syncthreads();   // ws(c)+xs(c) visible; stage ws_wr reads (chunk c-1) done

        if (c + 2 < NCH) {
            const char* src = wsrc0 + (size_t)(c + 2) * 65536;
            char* dst = wdst0 + ws_wr;
            #pragma unroll
            for (int i = 0; i < 8; i++) cp16(dst + i * 8192, src + i * 8192);
            CP_COMMIT();
        }
        if (c + 1 < NCH) {   // convert chunk c+1 from px regs
            const float* wbp = wb_s + (c + 1) * KCHUNK + cm * 8;
            float4 w0 = *(const float4*)(wbp);
            float4 w1 = *(const float4*)(wbp + 4);
            bacc = fmaf(px0.x, w0.x, bacc); bacc = fmaf(px0.y, w0.y, bacc);
            bacc = fmaf(px0.z, w0.z, bacc); bacc = fmaf(px0.w, w0.w, bacc);
            bacc = fmaf(px1.x, w1.x, bacc); bacc = fmaf(px1.y, w1.y, bacc);
            bacc = fmaf(px1.z, w1.z, bacc); bacc = fmaf(px1.w, w1.w, bacc);
            __half2* xsp = (__half2*)(smc + XS_O + (xs_rd ^ 8192) + crow * 128);
            xsp[(((4 * cG + 0) ^ rsw) << 2) + wordsel] = __floats2half2_rn(px0.x, px0.y);
            xsp[(((4 * cG + 1) ^ rsw) << 2) + wordsel] = __floats2half2_rn(px0.z, px0.w);
            xsp[(((4 * cG + 2) ^ rsw) << 2) + wordsel] = __floats2half2_rn(px1.x, px1.y);
            xsp[(((4 * cG + 3) ^ rsw) << 2) + wordsel] = __floats2half2_rn(px1.z, px1.w);
        }
        if (c + 2 < NCH) {   // prefetch x chunk c+2
            px0 = *(const float4*)(xsrc + (c + 2) * KCHUNK);
            px1 = *(const float4*)(xsrc + (c + 2) * KCHUNK + 4);
        }

        // ---- MMA chunk c ----
        const char* xaddr = smc + XS_O + xs_rd + (mw * 32 + l4) * 128 + lk * 16;
        const char* baddr = smc + WS_O + ws_rd + (nw * 64 + l4) * 128 + lk * 16;
        #pragma unroll
        for (int G = 0; G < 2; G++) {
            const int go = (G << 6) ^ sw6;
            uint4 LA0 = *(const uint4*)(xaddr + go);
            uint4 LA1 = *(const uint4*)(xaddr + 1024 + go);
            uint4 LA2 = *(const uint4*)(xaddr + 2048 + go);
            uint4 LA3 = *(const uint4*)(xaddr + 3072 + go);
            #pragma unroll
            for (int j = 0; j < 8; j++) {
                uint4 LB = *(const uint4*)(baddr + j * 1024 + go);
                mma_f16(acc[0][j], LA0.x, LA1.x, LA0.y, LA1.y, LB.x, LB.y);
                mma_f16(acc[1][j], LA2.x, LA3.x, LA2.y, LA3.y, LB.x, LB.y);
                mma_f16(acc[0][j], LA0.z, LA1.z, LA0.w, LA1.w, LB.z, LB.w);
                mma_f16(acc[1][j], LA2.z, LA3.z, LA2.w, LA3.w, LB.z, LB.w);
            }
        }

        ws_rd += 65536; if (ws_rd == 196608) ws_rd = 0;
        ws_wr += 65536; if (ws_wr == 196608) ws_wr = 0;
        xs_rd ^= 8192;
    }

    // ---- base reduce: 8 lanes (cm) per row ----
    bacc += __shfl_down_sync(0xffffffffu, bacc, 4, 8);
    bacc += __shfl_down_sync(0xffffffffu, bacc, 2, 8);
    bacc += __shfl_down_sync(0xffffffffu, bacc, 1, 8);
    if (cm == 0) base_s[crow] = bacc;

    // ---- per-row segmented scan over this warp's 64 cols ----
    float2 bhv[8];
    #pragma unroll
    for (int j = 0; j < 8; j++)
        bhv[j] = *(const float2*)(bh_s + nw * 64 + 8 * j + 2 * lk);

    #pragma unroll
    for (int i = 0; i < 2; i++) {
        #pragma unroll
        for (int hh = 0; hh < 2; hh++) {
            const int row = mw * 32 + 16 * i + 8 * hh + l4;
            float carry = 0.f;
            #pragma unroll
            for (int j = 0; j < 8; j++) {
                float v0 = fmaxf(acc[i][j][2 * hh]     + bhv[j].x, 0.f);
                float v1 = fmaxf(acc[i][j][2 * hh + 1] + bhv[j].y, 0.f);
                float p = v0 + v1;
                float incl = p, t;
                t = __shfl_up_sync(0xffffffffu, incl, 1, 4); if (lk >= 1) incl += t;
                t = __shfl_up_sync(0xffffffffu, incl, 2, 4); if (lk >= 2) incl += t;
                float excl = incl - p;
                acc[i][j][2 * hh]     = carry + excl + v0;
                acc[i][j][2 * hh + 1] = carry + incl;
                carry += __shfl_sync(0xffffffffu, incl, 3, 4);
            }
            if (lk == 0) seg_s[row * 8 + nw] = carry;
        }
    }
    __syncthreads();

    // ---- cross-warp segment prefix + base, store ----
    const float bbv = bb[0];
    #pragma unroll
    for (int i = 0; i < 2; i++) {
        #pragma unroll
        for (int hh = 0; hh < 2; hh++) {
            const int row = mw * 32 + 16 * i + 8 * hh + l4;
            float g = base_s[row] + bbv;
            #pragma unroll
            for (int s = 0; s < 8; s++)
                if (s < nw) g += seg_s[row * 8 + s];
            float* orow = out + (size_t)(row0 + row) * TDIM + nw * 64 + 2 * lk;
            #pragma unroll
            for (int j = 0; j < 8; j++) {
                float2 o;
                o.x = acc[i][j][2 * hh]     + g;
                o.y = acc[i][j][2 * hh + 1] + g;
                *(float2*)(orow + 8 * j) = o;
            }
        }
    }
}

extern "C" void kernel_launch(void* const* d_in, const int* in_sizes, int n_in,
                              void* d_out, int out_size)
{
    const float* x  = (const float*)d_in[0];
    const float* Wh = (const float*)d_in[1];
    const float* bh = (const float*)d_in[2];
    const float* Wb = (const float*)d_in[3];
    const float* bb = (const float*)d_in[4];
    float* out = (float*)d_out;
    (void)in_sizes; (void)n_in; (void)out_size;

    static bool attr_set = false;
    if (!attr_set) {
        cudaFuncSetAttribute(surv_f16b_kernel,
                             cudaFuncAttributeMaxDynamicSharedMemorySize,
                             SMEM_BYTES);
        attr_set = true;
    }

    prep_wh_kernel<<<TDIM, 256>>>(Wh);
    surv_f16b_kernel<<<BROWS / MTILE, NTHREADS, SMEM_BYTES>>>(x, bh, Wb, bb, out);
}

// round 8
// speedup vs baseline: 2.2025x; 1.0496x over previous
#include <cuda_runtime.h>
#include <cuda_fp16.h>
#include <cstdint>

// out[b,t] = cumsum_t( relu(x @ Wh^T + bh) ) + (x @ Wb^T + bb)
//   x [16384,1024] f32, Wh [512,1024] f32, bh[512], Wb[1,1024], bb[1]
//
// fp16 mma.sync m16n8k16. CTA = 32 rows x 512 cols, 256 threads (8 warps,
// warp tile 32x64), TWO CTAs per SM. KCHUNK=32, 32 chunks. Wh pre-converted
// to fp16 in FRAGMENT-ORDER layout (prepass) -> cp.async lands MMA-ready
// tiles; all fragment LDS.128 are at base+lane*16 (conflict-free, no XOR).
// x: LDG float4 prefetch -> fp16 convert -> STS into 2-stage xs.
// In-register scan epilogue + fused fp32 base GEMV.

#define DDIM   1024
#define TDIM   512
#define BROWS  16384
#define MTILE  32
#define KCHUNK 32
#define NCH    32
#define NTHREADS 256

// smem byte offsets
#define WS_O   0                      // 3 x 32768 ws ring
#define XS_O   98304                  // 2 x 2048 fp16 x (fragment order)
#define WB_O   102400                 // 1024 f32
#define BH_O   106496                 // 512 f32
#define BASE_O 108544                 // 32 f32
#define SEG_O  108672                 // 32*8 f32
#define SMEM_BYTES 109696

__device__ __half g_whs[TDIM * DDIM];  // [chunk][col-tile jg][lane][8 halfs]

__device__ __forceinline__ void mma_f16(float* c, uint32_t a0, uint32_t a1,
                                        uint32_t a2, uint32_t a3,
                                        uint32_t b0, uint32_t b1) {
    asm volatile(
        "mma.sync.aligned.m16n8k16.row.col.f32.f16.f16.f32 "
        "{%0,%1,%2,%3}, {%4,%5,%6,%7}, {%8,%9}, {%0,%1,%2,%3};"
        : "+f"(c[0]), "+f"(c[1]), "+f"(c[2]), "+f"(c[3])
        : "r"(a0), "r"(a1), "r"(a2), "r"(a3), "r"(b0), "r"(b1));
}
__device__ __forceinline__ void cp16(void* dst_s, const void* src_g) {
    uint32_t d = (uint32_t)__cvta_generic_to_shared(dst_s);
    asm volatile("cp.async.cg.shared.global [%0], [%1], 16;" :: "r"(d), "l"(src_g));
}
#define CP_COMMIT() asm volatile("cp.async.commit_group;" ::: "memory")

// prepass: Wh -> fp16 fragment-order:
//   (t,k): c=k>>5, G=(k>>4)&1, u=(k>>3)&1, lk=(k&7)>>1, w=k&1
//   jg=t>>3, l4=t&7, lane=4*l4+lk, h=4*G+2*u+w
//   half_idx = c*16384 + jg*256 + lane*8 + h
__global__ void __launch_bounds__(256) prep_wh_kernel(const float* __restrict__ Wh) {
    const int t  = blockIdx.x;
    const int k4 = threadIdx.x * 4;
    float4 v = *(const float4*)(Wh + (size_t)t * DDIM + k4);
    const int jg = t >> 3, l4 = t & 7;
    #pragma unroll
    for (int e = 0; e < 4; e++) {
        int k = k4 + e;
        int c = k >> 5, G = (k >> 4) & 1, u = (k >> 3) & 1;
        int lk = (k & 7) >> 1, w = k & 1;
        int lane = 4 * l4 + lk;
        int h = 4 * G + 2 * u + w;
        g_whs[(size_t)c * 16384 + jg * 256 + lane * 8 + h] =
            __float2half_rn(((const float*)&v)[e]);
    }
}

__global__ void __launch_bounds__(NTHREADS, 2)
surv_f16c_kernel(const float* __restrict__ x,
                 const float* __restrict__ bh,
                 const float* __restrict__ Wb,
                 const float* __restrict__ bb,
                 float* __restrict__ out)
{
    extern __shared__ char smc[];
    float* wb_s   = (float*)(smc + WB_O);
    float* bh_s   = (float*)(smc + BH_O);
    float* base_s = (float*)(smc + BASE_O);
    float* seg_s  = (float*)(smc + SEG_O);

    const int tid  = threadIdx.x;
    const int nw   = tid >> 5;         // warp = 64-col group (0..7)
    const int lane = tid & 31;
    const int l4   = lane >> 2;
    const int lk   = lane & 3;
    const int row0 = blockIdx.x * MTILE;

    // ws copy addressing: 32KB/chunk, 256 thr x 8 cp16
    const char* wsrc0 = (const char*)g_whs + tid * 16;
    char*       wdst0 = smc + WS_O + tid * 16;

    // x convert addressing: row = tid>>3 (0..31), kq = tid&7 (float4 of k)
    const int row = tid >> 3;
    const int kq  = tid & 7;
    const float* xsrc = x + (size_t)(row0 + row) * DDIM + kq * 4;
    // fragment slot: i=row>>4, G=kq>>2, u=(kq>>1)&1, lk_a=2*(kq&1),
    // rhalf=(row>>3)&1, lane_a=4*(row&7)+lk_a
    const int conv_off = ((row >> 4) * 2 + (kq >> 2)) * 512 +
                         (4 * (row & 7) + 2 * (kq & 1)) * 16 +
                         ((row >> 3) & 1) * 4 + ((kq >> 1) & 1) * 8;

    float acc[2][8][4];
    #pragma unroll
    for (int i = 0; i < 2; i++)
        #pragma unroll
        for (int j = 0; j < 8; j++)
            #pragma unroll
            for (int q = 0; q < 4; q++) acc[i][j][q] = 0.f;
    float bacc = 0.f;

    // preload Wb + bh
    #pragma unroll
    for (int i = 0; i < 4; i++) wb_s[tid + 256 * i] = Wb[tid + 256 * i];
    bh_s[tid]       = bh[tid];
    bh_s[tid + 256] = bh[tid + 256];

    // ws prologue: stages 0,1
    #pragma unroll
    for (int i = 0; i < 8; i++) cp16(wdst0 + i * 4096, wsrc0 + i * 4096);
    CP_COMMIT();
    #pragma unroll
    for (int i = 0; i < 8; i++) cp16(wdst0 + 32768 + i * 4096, wsrc0 + 32768 + i * 4096);
    CP_COMMIT();

    __syncthreads();   // wb_s visible

    // chunk0 convert + base; prefetch chunk1
    float4 px = *(const float4*)(xsrc);
    {
        const float4 wv = *(const float4*)(wb_s + kq * 4);
        bacc = fmaf(px.x, wv.x, bacc); bacc = fmaf(px.y, wv.y, bacc);
        bacc = fmaf(px.z, wv.z, bacc); bacc = fmaf(px.w, wv.w, bacc);
        *(__half2*)(smc + XS_O + conv_off)      = __floats2half2_rn(px.x, px.y);
        *(__half2*)(smc + XS_O + conv_off + 16) = __floats2half2_rn(px.z, px.w);
    }
    px = *(const float4*)(xsrc + KCHUNK);

    int ws_rd = 0;
    int ws_wr = 65536;

    #pragma unroll 1
    for (int c = 0; c < NCH; c++) {
        if (c == NCH - 1) asm volatile("cp.async.wait_group 0;" ::: "memory");
        else              asm volatile("cp.async.wait_group 1;" ::: "memory");
        __syncthreads();   // ws(c)+xs(c) visible; stage ws_wr reads done

        if (c + 2 < NCH) {
            const char* src = wsrc0 + (size_t)(c + 2) * 32768;
            char* dst = wdst0 + ws_wr;
            #pragma unroll
            for (int i = 0; i < 8; i++) cp16(dst + i * 4096, src + i * 4096);
            CP_COMMIT();
        }
        if (c + 1 < NCH) {   // base fma + convert chunk c+1
            const float4 wv = *(const float4*)(wb_s + (c + 1) * KCHUNK + kq * 4);
            bacc = fmaf(px.x, wv.x, bacc); bacc = fmaf(px.y, wv.y, bacc);
            bacc = fmaf(px.z, wv.z, bacc); bacc = fmaf(px.w, wv.w, bacc);
            char* xb = smc + XS_O + ((c + 1) & 1) * 2048 + conv_off;
            *(__half2*)(xb)      = __floats2half2_rn(px.x, px.y);
            *(__half2*)(xb + 16) = __floats2half2_rn(px.z, px.w);
        }
        if (c + 2 < NCH)
            px = *(const float4*)(xsrc + (c + 2) * KCHUNK);

        // ---- MMA chunk c: 4 A-loads + 8 B-loads, all base+lane*16 ----
        const char* xaddr = smc + XS_O + (c & 1) * 2048 + lane * 16;
        const char* baddr = smc + WS_O + ws_rd + nw * 4096 + lane * 16;
        uint4 LA00 = *(const uint4*)(xaddr);            // i0 G0
        uint4 LA01 = *(const uint4*)(xaddr + 512);      // i0 G1
        uint4 LA10 = *(const uint4*)(xaddr + 1024);     // i1 G0
        uint4 LA11 = *(const uint4*)(xaddr + 1536);     // i1 G1
        #pragma unroll
        for (int j = 0; j < 8; j++) {
            uint4 LB = *(const uint4*)(baddr + j * 512);
            mma_f16(acc[0][j], LA00.x, LA00.y, LA00.z, LA00.w, LB.x, LB.y);
            mma_f16(acc[1][j], LA10.x, LA10.y, LA10.z, LA10.w, LB.x, LB.y);
            mma_f16(acc[0][j], LA01.x, LA01.y, LA01.z, LA01.w, LB.z, LB.w);
            mma_f16(acc[1][j], LA11.x, LA11.y, LA11.z, LA11.w, LB.z, LB.w);
        }

        ws_rd += 32768; if (ws_rd == 98304) ws_rd = 0;
        ws_wr += 32768; if (ws_wr == 98304) ws_wr = 0;
    }

    // ---- base reduce: 8 lanes (kq) per row ----
    bacc += __shfl_down_sync(0xffffffffu, bacc, 4, 8);
    bacc += __shfl_down_sync(0xffffffffu, bacc, 2, 8);
    bacc += __shfl_down_sync(0xffffffffu, bacc, 1, 8);
    if (kq == 0) base_s[row] = bacc;

    // ---- per-row segmented scan over this warp's 64 cols ----
    float2 bhv[8];
    #pragma unroll
    for (int j = 0; j < 8; j++)
        bhv[j] = *(const float2*)(bh_s + nw * 64 + 8 * j + 2 * lk);

    #pragma unroll
    for (int i = 0; i < 2; i++) {
        #pragma unroll
        for (int hh = 0; hh < 2; hh++) {
            const int r = 16 * i + 8 * hh + l4;
            float carry = 0.f;
            #pragma unroll
            for (int j = 0; j < 8; j++) {
                float v0 = fmaxf(acc[i][j][2 * hh]     + bhv[j].x, 0.f);
                float v1 = fmaxf(acc[i][j][2 * hh + 1] + bhv[j].y, 0.f);
                float p = v0 + v1;
                float incl = p, t;
                t = __shfl_up_sync(0xffffffffu, incl, 1, 4); if (lk >= 1) incl += t;
                t = __shfl_up_sync(0xffffffffu, incl, 2, 4); if (lk >= 2) incl += t;
                float excl = incl - p;
                acc[i][j][2 * hh]     = carry + excl + v0;
                acc[i][j][2 * hh + 1] = carry + incl;
                carry += __shfl_sync(0xffffffffu, incl, 3, 4);
            }
            if (lk == 0) seg_s[r * 8 + nw] = carry;
        }
    }
    __syncthreads();

    // ---- cross-warp segment prefix + base, store ----
    const float bbv = bb[0];
    #pragma unroll
    for (int i = 0; i < 2; i++) {
        #pragma unroll
        for (int hh = 0; hh < 2; hh++) {
            const int r = 16 * i + 8 * hh + l4;
            float g = base_s[r] + bbv;
            #pragma unroll
            for (int s = 0; s < 8; s++)
                if (s < nw) g += seg_s[r * 8 + s];
            float* orow = out + (size_t)(row0 + r) * TDIM + nw * 64 + 2 * lk;
            #pragma unroll
            for (int j = 0; j < 8; j++) {
                float2 o;
                o.x = acc[i][j][2 * hh]     + g;
                o.y = acc[i][j][2 * hh + 1] + g;
                *(float2*)(orow + 8 * j) = o;
            }
        }
    }
}

extern "C" void kernel_launch(void* const* d_in, const int* in_sizes, int n_in,
                              void* d_out, int out_size)
{
    const float* x  = (const float*)d_in[0];
    const float* Wh = (const float*)d_in[1];
    const float* bh = (const float*)d_in[2];
    const float* Wb = (const float*)d_in[3];
    const float* bb = (const float*)d_in[4];
    float* out = (float*)d_out;
    (void)in_sizes; (void)n_in; (void)out_size;

    static bool attr_set = false;
    if (!attr_set) {
        cudaFuncSetAttribute(surv_f16c_kernel,
                             cudaFuncAttributeMaxDynamicSharedMemorySize,
                             SMEM_BYTES);
        attr_set = true;
    }

    prep_wh_kernel<<<TDIM, 256>>>(Wh);
    surv_f16c_kernel<<<BROWS / MTILE, NTHREADS, SMEM_BYTES>>>(x, bh, Wb, bb, out);
}